// round 14
// baseline (speedup 1.0000x reference)
#include <cuda_runtime.h>
#include <cuda_bf16.h>
#include <cuda_fp16.h>
#include <cstdint>

#define NN 100000
#define EE 1600000
#define DIN 24
#define DH 64
#define DOUT 12
#define NEG_SLOPE 0.01f

#define HB    (EE / 256)              // 6250 hist/scatter blocks
#define EMB   (NN / 4)                // 25000 embed blocks
#define NB_SCAN ((NN + 1023) / 1024)  // 98
#define XB2   ((NN + 127) / 128)      // 782 xform blocks (128 nodes each)

// ---------------- scratch (static device globals; allocation-free) -----------
__device__ __align__(16) float  g_h[NN * DH];    // current node features
__device__ __align__(16) float  g_hs[NN * DH];   // h @ W_self.T
__device__ __align__(16) __half g_zh[NN * DH];   // h @ W_func.T (fp16, for gathers)
__device__ float g_ssrc[NN];
__device__ float g_sdst[NN];
__device__ int   g_rowstart[NN + 1];
__device__ int   g_cursor[NN];                   // counts; returns to 0 after scatter
__device__ __align__(16) int2 g_edge[EE];        // (src, bitcast(e_w)) sorted by dst
__device__ int   g_flags[128];                   // lookback flags (reset by k_sx)
__device__ int   g_aggval[128];
__device__ int   g_prefval[128];
__device__ float g_c[4];                         // {c1_l1, c0_l1, c1_l2, c0_l2}

#define LDSM4(r0, r1, r2, r3, addr) \
    asm volatile("ldmatrix.sync.aligned.m8n8.x4.shared.b16 {%0,%1,%2,%3},[%4];" \
                 : "=r"(r0), "=r"(r1), "=r"(r2), "=r"(r3) : "r"(addr))
#define LDSM2(r0, r1, addr) \
    asm volatile("ldmatrix.sync.aligned.m8n8.x2.shared.b16 {%0,%1},[%2];" \
                 : "=r"(r0), "=r"(r1) : "r"(addr))
#define MMA16816(c, a0, a1, a2, a3, b0, b1) \
    asm volatile("mma.sync.aligned.m16n8k16.row.col.f32.f16.f16.f32 " \
                 "{%0,%1,%2,%3},{%4,%5,%6,%7},{%8,%9},{%0,%1,%2,%3};" \
                 : "+f"((c)[0]), "+f"((c)[1]), "+f"((c)[2]), "+f"((c)[3]) \
                 : "r"(a0), "r"(a1), "r"(a2), "r"(a3), "r"(b0), "r"(b1))

// ---------------- fused: hist + input embedding + edge coeffs ----------------
__global__ __launch_bounds__(256) void k_pre(
    const int* __restrict__ dst, const float* __restrict__ feats,
    const float* __restrict__ W, const float* __restrict__ b,
    const float* __restrict__ eW, const float* __restrict__ eb,
    const float* __restrict__ a1, const float* __restrict__ a2) {
    __shared__ float w_sm[64 * 25];
    __shared__ float f_sm[4 * 25];
    __shared__ float b_sm[64];
    __shared__ float csh[4][64];
    int t = threadIdx.x;
    int blk = blockIdx.x;

    if (blk < HB) {
        int e = blk * 256 + t;
        atomicAdd(&g_cursor[dst[e]], 1);
    } else if (blk < HB + EMB) {
        int node0 = (blk - HB) * 4;
        for (int idx = t; idx < 64 * 24; idx += 256)
            w_sm[(idx / 24) * 25 + (idx % 24)] = W[idx];
        for (int idx = t; idx < 4 * 24; idx += 256)
            f_sm[(idx / 24) * 25 + (idx % 24)] = feats[(node0 + idx / 24) * 24 + (idx % 24)];
        if (t < 64) b_sm[t] = b[t];
        __syncthreads();
        int ch = t & 63, nl = t >> 6;
        float acc = b_sm[ch];
        #pragma unroll
        for (int k = 0; k < 24; k++)
            acc += f_sm[nl * 25 + k] * w_sm[ch * 25 + k];
        g_h[(node0 + nl) * 64 + ch] = acc;
    } else {
        if (t < 64) {
            csh[0][t] = eW[t] * a1[128 + t];
            csh[1][t] = eb[t] * a1[128 + t];
            csh[2][t] = eW[t] * a2[128 + t];
            csh[3][t] = eb[t] * a2[128 + t];
        }
        __syncthreads();
        if (t < 4) {
            float s = 0.f;
            #pragma unroll
            for (int k = 0; k < 64; k++) s += csh[t][k];
            g_c[t] = s;
        }
    }
}

// ---------------- single-pass scan (decoupled lookback) ----------------------
__global__ __launch_bounds__(256) void k_scan() {
    __shared__ int sh[256];
    __shared__ int s_pref;
    int t = threadIdx.x;
    int bid = blockIdx.x;
    int base = bid * 1024 + t * 4;
    int v[4];
    #pragma unroll
    for (int i = 0; i < 4; i++) v[i] = (base + i < NN) ? g_cursor[base + i] : 0;
    int s = v[0] + v[1] + v[2] + v[3];
    sh[t] = s;
    __syncthreads();
    for (int off = 1; off < 256; off <<= 1) {
        int x = 0;
        if (t >= off) x = sh[t - off];
        __syncthreads();
        if (t >= off) sh[t] += x;
        __syncthreads();
    }
    int total = sh[255];
    int run = sh[t] - s;

    if (t == 0) {
        g_aggval[bid] = total;
        __threadfence();
        atomicExch(&g_flags[bid], 1);
        int pref = 0;
        int j = bid - 1;
        while (j >= 0) {
            int f;
            do { f = atomicAdd(&g_flags[j], 0); } while (f == 0);
            if (f == 2) { pref += atomicAdd(&g_prefval[j], 0); break; }
            pref += atomicAdd(&g_aggval[j], 0);
            j--;
        }
        g_prefval[bid] = pref + total;
        __threadfence();
        atomicExch(&g_flags[bid], 2);
        s_pref = pref;
    }
    __syncthreads();
    int add = s_pref;
    #pragma unroll
    for (int i = 0; i < 4; i++) {
        if (base + i < NN) g_rowstart[base + i] = add + run;
        run += v[i];
    }
    if (bid == 0 && t == 0) g_rowstart[NN] = EE;
}

// ---------------- xform body (fp16 HMMA, 128 nodes) --------------------------
__device__ __forceinline__ void xform_body(int node0, const float* __restrict__ Wself,
                                           const float* __restrict__ Wfunc,
                                           const float* __restrict__ attn,
                                           __half* hSm, __half* wSm) {
    int t = threadIdx.x;

    // ---- stage h -> fp16 ----
    {
        int node = t >> 1;
        int k0 = (t & 1) * 32;
        int gn = node0 + node;
        #pragma unroll
        for (int i = 0; i < 8; i++) {
            float4 f = (gn < NN) ? *(const float4*)(g_h + (size_t)gn * 64 + k0 + i * 4)
                                 : make_float4(0.f, 0.f, 0.f, 0.f);
            *(__half2*)(hSm + node * 72 + k0 + i * 4)     = __floats2half2_rn(f.x, f.y);
            *(__half2*)(hSm + node * 72 + k0 + i * 4 + 2) = __floats2half2_rn(f.z, f.w);
        }
    }
    // ---- stage W -> fp16 ----
    {
        int row = t >> 1;
        int k0 = (t & 1) * 32;
        const float* Wr = (row < 64) ? (Wself + row * 64) : (Wfunc + (row - 64) * 64);
        #pragma unroll
        for (int i = 0; i < 8; i++) {
            float4 f = *(const float4*)(Wr + k0 + i * 4);
            *(__half2*)(wSm + row * 72 + k0 + i * 4)     = __floats2half2_rn(f.x, f.y);
            *(__half2*)(wSm + row * 72 + k0 + i * 4 + 2) = __floats2half2_rn(f.z, f.w);
        }
    }
    __syncthreads();

    int w = t >> 5, lane = t & 31;
    int mtp = w & 3;       // node tile pair: tiles mtp and mtp+4
    int mh = w >> 2;       // 0 = self, 1 = func

    uint32_t aB0 = (uint32_t)__cvta_generic_to_shared(
        hSm + (mtp * 16 + (lane & 15)) * 72 + ((lane >> 4) << 3));
    uint32_t aB1 = aB0 + (uint32_t)(64 * 72 * 2);
    uint32_t bB = (uint32_t)__cvta_generic_to_shared(
        wSm + (mh * 64 + (lane & 7)) * 72 + (((lane >> 3) & 1) << 3));

    float acc[2][8][4];
    #pragma unroll
    for (int m = 0; m < 2; m++)
        #pragma unroll
        for (int nt = 0; nt < 8; nt++)
            #pragma unroll
            for (int i = 0; i < 4; i++) acc[m][nt][i] = 0.f;

    #pragma unroll
    for (int ks = 0; ks < 4; ks++) {
        uint32_t a00, a01, a02, a03, a10, a11, a12, a13;
        LDSM4(a00, a01, a02, a03, aB0 + ks * 32);
        LDSM4(a10, a11, a12, a13, aB1 + ks * 32);
        #pragma unroll
        for (int nt = 0; nt < 8; nt++) {
            uint32_t b0, b1;
            LDSM2(b0, b1, bB + nt * (8 * 72 * 2) + ks * 32);
            MMA16816(acc[0][nt], a00, a01, a02, a03, b0, b1);
            MMA16816(acc[1][nt], a10, a11, a12, a13, b0, b1);
        }
    }

    int row = lane >> 2;
    int col2 = (lane & 3) * 2;
    const unsigned FULL = 0xffffffffu;

    #pragma unroll
    for (int m = 0; m < 2; m++) {
        int gnl = node0 + (mtp + m * 4) * 16 + row;
        int gnh = gnl + 8;
        if (mh == 0) {
            #pragma unroll
            for (int nt = 0; nt < 8; nt++) {
                int ch = nt * 8 + col2;
                if (gnl < NN)
                    *(float2*)(g_hs + (size_t)gnl * 64 + ch) =
                        make_float2(acc[m][nt][0], acc[m][nt][1]);
                if (gnh < NN)
                    *(float2*)(g_hs + (size_t)gnh * 64 + ch) =
                        make_float2(acc[m][nt][2], acc[m][nt][3]);
            }
        } else {
            float psl = 0.f, psh = 0.f, pdl = 0.f, pdh = 0.f;
            #pragma unroll
            for (int nt = 0; nt < 8; nt++) {
                int chF = nt * 8 + col2;
                if (gnl < NN)
                    *(__half2*)(g_zh + (size_t)gnl * 64 + chF) =
                        __floats2half2_rn(acc[m][nt][0], acc[m][nt][1]);
                if (gnh < NN)
                    *(__half2*)(g_zh + (size_t)gnh * 64 + chF) =
                        __floats2half2_rn(acc[m][nt][2], acc[m][nt][3]);
                float as0 = attn[chF], as1 = attn[chF + 1];
                float ad0 = attn[64 + chF], ad1 = attn[64 + chF + 1];
                psl += acc[m][nt][0] * as0 + acc[m][nt][1] * as1;
                psh += acc[m][nt][2] * as0 + acc[m][nt][3] * as1;
                pdl += acc[m][nt][0] * ad0 + acc[m][nt][1] * ad1;
                pdh += acc[m][nt][2] * ad0 + acc[m][nt][3] * ad1;
            }
            #pragma unroll
            for (int off = 1; off <= 2; off <<= 1) {
                psl += __shfl_xor_sync(FULL, psl, off);
                psh += __shfl_xor_sync(FULL, psh, off);
                pdl += __shfl_xor_sync(FULL, pdl, off);
                pdh += __shfl_xor_sync(FULL, pdh, off);
            }
            if ((lane & 3) == 0) {
                if (gnl < NN) { g_ssrc[gnl] = psl; g_sdst[gnl] = pdl; }
                if (gnh < NN) { g_ssrc[gnh] = psh; g_sdst[gnh] = pdh; }
            }
        }
    }
}

// ---------------- fused: scatter + xform layer 1 + flag reset ----------------
__global__ __launch_bounds__(256) void k_sx(const int* __restrict__ src,
                                            const int* __restrict__ dst,
                                            const float* __restrict__ ew,
                                            const float* __restrict__ Wself,
                                            const float* __restrict__ Wfunc,
                                            const float* __restrict__ attn) {
    __shared__ __half hSm[128 * 72];
    __shared__ __half wSm[128 * 72];
    int blk = blockIdx.x;
    if (blk < HB) {
        if (blk == 0 && threadIdx.x < 128) g_flags[threadIdx.x] = 0;
        int e = blk * 256 + threadIdx.x;
        int d = dst[e];
        int p = g_rowstart[d] + atomicSub(&g_cursor[d], 1) - 1;  // cursor -> 0
        g_edge[p] = make_int2(src[e], __float_as_int(ew[e]));
    } else {
        xform_body((blk - HB) * 128, Wself, Wfunc, attn, hSm, wSm);
    }
}

// ---------------- xform layer 2 ----------------------------------------------
__global__ __launch_bounds__(256) void k_xform2(const float* __restrict__ Wself,
                                                const float* __restrict__ Wfunc,
                                                const float* __restrict__ attn) {
    __shared__ __half hSm[128 * 72];
    __shared__ __half wSm[128 * 72];
    xform_body(blockIdx.x * 128, Wself, Wfunc, attn, hSm, wSm);
}

// ---------------- edge aggregation (half-warp paired edges) ------------------
// Warp processes 2 edges/step: half-warp h handles edge j+h, lane owns 4 ch
// (uint2 of fp16). Halves combine via one xor-16 shfl-add.
__global__ __launch_bounds__(256) void k_agg(int layer, const float* __restrict__ linW,
                                             const float* __restrict__ linb,
                                             float* __restrict__ out) {
    __shared__ float w_sm[12][64];
    __shared__ float b_sm[12];
    int t = threadIdx.x;
    if (layer) {
        for (int idx = t; idx < 12 * 64; idx += 256)
            w_sm[idx >> 6][idx & 63] = linW[idx];
        if (t < 12) b_sm[t] = linb[t];
        __syncthreads();
    }

    int n = blockIdx.x * 8 + (t >> 5);
    int lane = t & 31;
    int half = lane >> 4;    // 0,1
    int hl = lane & 15;      // lane within half
    float c1 = g_c[layer * 2 + 0];
    float c0 = g_c[layer * 2 + 1];
    int beg = g_rowstart[n];
    int end = g_rowstart[n + 1];
    float base = g_sdst[n] + c0;
    const unsigned FULL = 0xffffffffu;

    float ac0 = 0.f, ac1 = 0.f, ac2 = 0.f, ac3 = 0.f, den = 0.f;

    for (int i0 = beg; i0 < end; i0 += 32) {
        int rem = end - i0;
        if (rem > 32) rem = 32;
        int idx = i0 + (lane < rem ? lane : 0);
        int2 e = g_edge[idx];
        float v = g_ssrc[e.x] + base + c1 * __int_as_float(e.y);
        v = fmaxf(v, NEG_SLOPE * v);
        float x = (lane < rem) ? __expf(v) : 0.f;
        int srcid = e.x;

        #pragma unroll 4
        for (int j = 0; j < rem; j += 2) {
            int eidx = j + half;                       // <= 31 always
            float xj = __shfl_sync(FULL, x, eidx);     // 0 for eidx >= rem
            int   sj = __shfl_sync(FULL, srcid, eidx); // clamped-valid address
            uint2 zb = *(const uint2*)(g_zh + (size_t)sj * 64 + hl * 4);
            float2 zlo = __half22float2(*(__half2*)&zb.x);
            float2 zhi = __half22float2(*(__half2*)&zb.y);
            den += xj;
            ac0 += xj * zlo.x;
            ac1 += xj * zlo.y;
            ac2 += xj * zhi.x;
            ac3 += xj * zhi.y;
        }
    }

    // combine halves (each lane ends with full sums for channels hl*4..hl*4+3)
    den += __shfl_xor_sync(FULL, den, 16);
    ac0 += __shfl_xor_sync(FULL, ac0, 16);
    ac1 += __shfl_xor_sync(FULL, ac1, 16);
    ac2 += __shfl_xor_sync(FULL, ac2, 16);
    ac3 += __shfl_xor_sync(FULL, ac3, 16);

    // this lane writes channels hl*4 + half*2 + {0,1}
    float a0 = half ? ac2 : ac0;
    float a1 = half ? ac3 : ac1;
    size_t o = (size_t)n * 64 + hl * 4 + half * 2;

    float2 hv = *(const float2*)(g_h + o);
    float r0, r1;
    if (end > beg) {
        float inv = 1.0f / den;
        float2 hsv = *(const float2*)(g_hs + o);
        r0 = hsv.x + a0 * inv;
        r1 = hsv.y + a1 * inv;
    } else {
        r0 = hv.x; r1 = hv.y;
    }
    float hn0 = hv.x + fmaxf(r0, 0.f);
    float hn1 = hv.y + fmaxf(r1, 0.f);

    if (!layer) {
        *(float2*)(g_h + o) = make_float2(hn0, hn1);
    } else {
        int chb = hl * 4 + half * 2;
        float yv = 0.f;
        #pragma unroll
        for (int c = 0; c < 12; c++) {
            float2 wv = *(const float2*)&w_sm[c][chb];
            float p = hn0 * wv.x + hn1 * wv.y;
            #pragma unroll
            for (int off = 16; off > 0; off >>= 1)
                p += __shfl_xor_sync(FULL, p, off);
            if (lane == c) yv = p + b_sm[c];
        }
        if (lane < 12) out[n * 12 + lane] = yv;
    }
}

// ---------------- launch -----------------------------------------------------
extern "C" void kernel_launch(void* const* d_in, const int* in_sizes, int n_in,
                              void* d_out, int out_size) {
    const float* feats   = (const float*)d_in[0];
    const float* e_w     = (const float*)d_in[1];
    const int*   src     = (const int*)d_in[4];
    const int*   dst     = (const int*)d_in[5];
    const float* emb_h_W = (const float*)d_in[6];
    const float* emb_h_b = (const float*)d_in[7];
    const float* emb_e_W = (const float*)d_in[8];
    const float* emb_e_b = (const float*)d_in[9];
    const float* W_self1 = (const float*)d_in[10];
    const float* W_func1 = (const float*)d_in[11];
    const float* attn1   = (const float*)d_in[12];
    const float* W_self2 = (const float*)d_in[13];
    const float* W_func2 = (const float*)d_in[14];
    const float* attn2   = (const float*)d_in[15];
    const float* lin1_W  = (const float*)d_in[16];
    const float* lin1_b  = (const float*)d_in[17];
    float* out = (float*)d_out;

    // ncu captures the 4th kernel launch -> k_agg(layer 0)
    k_pre<<<HB + EMB + 1, 256>>>(dst, feats, emb_h_W, emb_h_b,
                                 emb_e_W, emb_e_b, attn1, attn2);    // 0
    k_scan<<<NB_SCAN, 256>>>();                                      // 1
    k_sx<<<HB + XB2, 256>>>(src, dst, e_w, W_self1, W_func1, attn1); // 2
    k_agg<<<NN / 8, 256>>>(0, lin1_W, lin1_b, out);                  // 3 <- ncu
    k_xform2<<<XB2, 256>>>(W_self2, W_func2, attn2);                 // 4
    k_agg<<<NN / 8, 256>>>(1, lin1_W, lin1_b, out);                  // 5
}

// round 15
// speedup vs baseline: 1.1006x; 1.1006x over previous
#include <cuda_runtime.h>
#include <cuda_bf16.h>
#include <cuda_fp16.h>
#include <cstdint>

#define NN 100000
#define EE 1600000
#define DIN 24
#define DH 64
#define DOUT 12
#define NEG_SLOPE 0.01f

#define HB    (EE / 256)              // 6250 hist/scatter blocks
#define EMB   (NN / 4)                // 25000 embed blocks
#define NB_SCAN ((NN + 1023) / 1024)  // 98
#define XB2   ((NN + 127) / 128)      // 782 xform blocks (128 nodes each)

// ---------------- scratch (static device globals; allocation-free) -----------
__device__ __align__(16) float  g_h[NN * DH];    // current node features
__device__ __align__(16) float  g_hs[NN * DH];   // h @ W_self.T
__device__ __align__(16) __half g_zh[NN * DH];   // h @ W_func.T (fp16, for gathers)
__device__ float g_ssrc[NN];
__device__ float g_sdst[NN];
__device__ int   g_rowstart[NN + 1];
__device__ int   g_cursor[NN];                   // counts; returns to 0 after scatter
__device__ __align__(16) int2 g_edge[EE];        // (src, bitcast(e_w)) sorted by dst
__device__ int   g_flags[128];                   // lookback flags (reset by k_sx)
__device__ int   g_aggval[128];
__device__ int   g_prefval[128];
__device__ float g_c[4];                         // {c1_l1, c0_l1, c1_l2, c0_l2}

#define LDSM4(r0, r1, r2, r3, addr) \
    asm volatile("ldmatrix.sync.aligned.m8n8.x4.shared.b16 {%0,%1,%2,%3},[%4];" \
                 : "=r"(r0), "=r"(r1), "=r"(r2), "=r"(r3) : "r"(addr))
#define LDSM2(r0, r1, addr) \
    asm volatile("ldmatrix.sync.aligned.m8n8.x2.shared.b16 {%0,%1},[%2];" \
                 : "=r"(r0), "=r"(r1) : "r"(addr))
#define MMA16816(c, a0, a1, a2, a3, b0, b1) \
    asm volatile("mma.sync.aligned.m16n8k16.row.col.f32.f16.f16.f32 " \
                 "{%0,%1,%2,%3},{%4,%5,%6,%7},{%8,%9},{%0,%1,%2,%3};" \
                 : "+f"((c)[0]), "+f"((c)[1]), "+f"((c)[2]), "+f"((c)[3]) \
                 : "r"(a0), "r"(a1), "r"(a2), "r"(a3), "r"(b0), "r"(b1))

// ---------------- fused: hist + input embedding + edge coeffs ----------------
__global__ __launch_bounds__(256) void k_pre(
    const int* __restrict__ dst, const float* __restrict__ feats,
    const float* __restrict__ W, const float* __restrict__ b,
    const float* __restrict__ eW, const float* __restrict__ eb,
    const float* __restrict__ a1, const float* __restrict__ a2) {
    __shared__ float w_sm[64 * 25];
    __shared__ float f_sm[4 * 25];
    __shared__ float b_sm[64];
    __shared__ float csh[4][64];
    int t = threadIdx.x;
    int blk = blockIdx.x;

    if (blk < HB) {
        int e = blk * 256 + t;
        atomicAdd(&g_cursor[dst[e]], 1);
    } else if (blk < HB + EMB) {
        int node0 = (blk - HB) * 4;
        for (int idx = t; idx < 64 * 24; idx += 256)
            w_sm[(idx / 24) * 25 + (idx % 24)] = W[idx];
        for (int idx = t; idx < 4 * 24; idx += 256)
            f_sm[(idx / 24) * 25 + (idx % 24)] = feats[(node0 + idx / 24) * 24 + (idx % 24)];
        if (t < 64) b_sm[t] = b[t];
        __syncthreads();
        int ch = t & 63, nl = t >> 6;
        float acc = b_sm[ch];
        #pragma unroll
        for (int k = 0; k < 24; k++)
            acc += f_sm[nl * 25 + k] * w_sm[ch * 25 + k];
        g_h[(node0 + nl) * 64 + ch] = acc;
    } else {
        if (t < 64) {
            csh[0][t] = eW[t] * a1[128 + t];
            csh[1][t] = eb[t] * a1[128 + t];
            csh[2][t] = eW[t] * a2[128 + t];
            csh[3][t] = eb[t] * a2[128 + t];
        }
        __syncthreads();
        if (t < 4) {
            float s = 0.f;
            #pragma unroll
            for (int k = 0; k < 64; k++) s += csh[t][k];
            g_c[t] = s;
        }
    }
}

// ---------------- single-pass scan (decoupled lookback) ----------------------
__global__ __launch_bounds__(256) void k_scan() {
    __shared__ int sh[256];
    __shared__ int s_pref;
    int t = threadIdx.x;
    int bid = blockIdx.x;
    int base = bid * 1024 + t * 4;
    int v[4];
    #pragma unroll
    for (int i = 0; i < 4; i++) v[i] = (base + i < NN) ? g_cursor[base + i] : 0;
    int s = v[0] + v[1] + v[2] + v[3];
    sh[t] = s;
    __syncthreads();
    for (int off = 1; off < 256; off <<= 1) {
        int x = 0;
        if (t >= off) x = sh[t - off];
        __syncthreads();
        if (t >= off) sh[t] += x;
        __syncthreads();
    }
    int total = sh[255];
    int run = sh[t] - s;

    if (t == 0) {
        g_aggval[bid] = total;
        __threadfence();
        atomicExch(&g_flags[bid], 1);
        int pref = 0;
        int j = bid - 1;
        while (j >= 0) {
            int f;
            do { f = atomicAdd(&g_flags[j], 0); } while (f == 0);
            if (f == 2) { pref += atomicAdd(&g_prefval[j], 0); break; }
            pref += atomicAdd(&g_aggval[j], 0);
            j--;
        }
        g_prefval[bid] = pref + total;
        __threadfence();
        atomicExch(&g_flags[bid], 2);
        s_pref = pref;
    }
    __syncthreads();
    int add = s_pref;
    #pragma unroll
    for (int i = 0; i < 4; i++) {
        if (base + i < NN) g_rowstart[base + i] = add + run;
        run += v[i];
    }
    if (bid == 0 && t == 0) g_rowstart[NN] = EE;
}

// ---------------- xform body (fp16 HMMA, 128 nodes) --------------------------
__device__ __forceinline__ void xform_body(int node0, const float* __restrict__ Wself,
                                           const float* __restrict__ Wfunc,
                                           const float* __restrict__ attn,
                                           __half* hSm, __half* wSm) {
    int t = threadIdx.x;

    // ---- stage h -> fp16 ----
    {
        int node = t >> 1;
        int k0 = (t & 1) * 32;
        int gn = node0 + node;
        #pragma unroll
        for (int i = 0; i < 8; i++) {
            float4 f = (gn < NN) ? *(const float4*)(g_h + (size_t)gn * 64 + k0 + i * 4)
                                 : make_float4(0.f, 0.f, 0.f, 0.f);
            *(__half2*)(hSm + node * 72 + k0 + i * 4)     = __floats2half2_rn(f.x, f.y);
            *(__half2*)(hSm + node * 72 + k0 + i * 4 + 2) = __floats2half2_rn(f.z, f.w);
        }
    }
    // ---- stage W -> fp16 ----
    {
        int row = t >> 1;
        int k0 = (t & 1) * 32;
        const float* Wr = (row < 64) ? (Wself + row * 64) : (Wfunc + (row - 64) * 64);
        #pragma unroll
        for (int i = 0; i < 8; i++) {
            float4 f = *(const float4*)(Wr + k0 + i * 4);
            *(__half2*)(wSm + row * 72 + k0 + i * 4)     = __floats2half2_rn(f.x, f.y);
            *(__half2*)(wSm + row * 72 + k0 + i * 4 + 2) = __floats2half2_rn(f.z, f.w);
        }
    }
    __syncthreads();

    int w = t >> 5, lane = t & 31;
    int mtp = w & 3;       // node tile pair: tiles mtp and mtp+4
    int mh = w >> 2;       // 0 = self, 1 = func

    uint32_t aB0 = (uint32_t)__cvta_generic_to_shared(
        hSm + (mtp * 16 + (lane & 15)) * 72 + ((lane >> 4) << 3));
    uint32_t aB1 = aB0 + (uint32_t)(64 * 72 * 2);
    uint32_t bB = (uint32_t)__cvta_generic_to_shared(
        wSm + (mh * 64 + (lane & 7)) * 72 + (((lane >> 3) & 1) << 3));

    float acc[2][8][4];
    #pragma unroll
    for (int m = 0; m < 2; m++)
        #pragma unroll
        for (int nt = 0; nt < 8; nt++)
            #pragma unroll
            for (int i = 0; i < 4; i++) acc[m][nt][i] = 0.f;

    #pragma unroll
    for (int ks = 0; ks < 4; ks++) {
        uint32_t a00, a01, a02, a03, a10, a11, a12, a13;
        LDSM4(a00, a01, a02, a03, aB0 + ks * 32);
        LDSM4(a10, a11, a12, a13, aB1 + ks * 32);
        #pragma unroll
        for (int nt = 0; nt < 8; nt++) {
            uint32_t b0, b1;
            LDSM2(b0, b1, bB + nt * (8 * 72 * 2) + ks * 32);
            MMA16816(acc[0][nt], a00, a01, a02, a03, b0, b1);
            MMA16816(acc[1][nt], a10, a11, a12, a13, b0, b1);
        }
    }

    int row = lane >> 2;
    int col2 = (lane & 3) * 2;
    const unsigned FULL = 0xffffffffu;

    #pragma unroll
    for (int m = 0; m < 2; m++) {
        int gnl = node0 + (mtp + m * 4) * 16 + row;
        int gnh = gnl + 8;
        if (mh == 0) {
            #pragma unroll
            for (int nt = 0; nt < 8; nt++) {
                int ch = nt * 8 + col2;
                if (gnl < NN)
                    *(float2*)(g_hs + (size_t)gnl * 64 + ch) =
                        make_float2(acc[m][nt][0], acc[m][nt][1]);
                if (gnh < NN)
                    *(float2*)(g_hs + (size_t)gnh * 64 + ch) =
                        make_float2(acc[m][nt][2], acc[m][nt][3]);
            }
        } else {
            float psl = 0.f, psh = 0.f, pdl = 0.f, pdh = 0.f;
            #pragma unroll
            for (int nt = 0; nt < 8; nt++) {
                int chF = nt * 8 + col2;
                if (gnl < NN)
                    *(__half2*)(g_zh + (size_t)gnl * 64 + chF) =
                        __floats2half2_rn(acc[m][nt][0], acc[m][nt][1]);
                if (gnh < NN)
                    *(__half2*)(g_zh + (size_t)gnh * 64 + chF) =
                        __floats2half2_rn(acc[m][nt][2], acc[m][nt][3]);
                float as0 = attn[chF], as1 = attn[chF + 1];
                float ad0 = attn[64 + chF], ad1 = attn[64 + chF + 1];
                psl += acc[m][nt][0] * as0 + acc[m][nt][1] * as1;
                psh += acc[m][nt][2] * as0 + acc[m][nt][3] * as1;
                pdl += acc[m][nt][0] * ad0 + acc[m][nt][1] * ad1;
                pdh += acc[m][nt][2] * ad0 + acc[m][nt][3] * ad1;
            }
            #pragma unroll
            for (int off = 1; off <= 2; off <<= 1) {
                psl += __shfl_xor_sync(FULL, psl, off);
                psh += __shfl_xor_sync(FULL, psh, off);
                pdl += __shfl_xor_sync(FULL, pdl, off);
                pdh += __shfl_xor_sync(FULL, pdh, off);
            }
            if ((lane & 3) == 0) {
                if (gnl < NN) { g_ssrc[gnl] = psl; g_sdst[gnl] = pdl; }
                if (gnh < NN) { g_ssrc[gnh] = psh; g_sdst[gnh] = pdh; }
            }
        }
    }
}

// ---------------- fused: scatter + xform layer 1 + flag reset ----------------
__global__ __launch_bounds__(256) void k_sx(const int* __restrict__ src,
                                            const int* __restrict__ dst,
                                            const float* __restrict__ ew,
                                            const float* __restrict__ Wself,
                                            const float* __restrict__ Wfunc,
                                            const float* __restrict__ attn) {
    __shared__ __half hSm[128 * 72];
    __shared__ __half wSm[128 * 72];
    int blk = blockIdx.x;
    if (blk < HB) {
        if (blk == 0 && threadIdx.x < 128) g_flags[threadIdx.x] = 0;
        int e = blk * 256 + threadIdx.x;
        int d = dst[e];
        int p = g_rowstart[d] + atomicSub(&g_cursor[d], 1) - 1;  // cursor -> 0
        g_edge[p] = make_int2(src[e], __float_as_int(ew[e]));
    } else {
        xform_body((blk - HB) * 128, Wself, Wfunc, attn, hSm, wSm);
    }
}

// ---------------- xform layer 2 ----------------------------------------------
__global__ __launch_bounds__(256) void k_xform2(const float* __restrict__ Wself,
                                                const float* __restrict__ Wfunc,
                                                const float* __restrict__ attn) {
    __shared__ __half hSm[128 * 72];
    __shared__ __half wSm[128 * 72];
    xform_body(blockIdx.x * 128, Wself, Wfunc, attn, hSm, wSm);
}

// ---------------- edge aggregation (warp per node, smem edge broadcast) ------
// Batch preamble stores (x, src) per lane to smem; unroll-8 inner loop reads
// via one LDS.64 broadcast per edge, 8 z-gathers in flight.
__global__ __launch_bounds__(256) void k_agg(int layer, const float* __restrict__ linW,
                                             const float* __restrict__ linb,
                                             float* __restrict__ out) {
    __shared__ float w_sm[12][64];
    __shared__ float b_sm[12];
    __shared__ __align__(8) float2 ebuf[8][32];   // per-warp (x, bitcast src)
    int t = threadIdx.x;
    if (layer) {
        for (int idx = t; idx < 12 * 64; idx += 256)
            w_sm[idx >> 6][idx & 63] = linW[idx];
        if (t < 12) b_sm[t] = linb[t];
        __syncthreads();
    }

    int wid = t >> 5;
    int n = blockIdx.x * 8 + wid;
    int lane = t & 31;
    float c1 = g_c[layer * 2 + 0];
    float c0 = g_c[layer * 2 + 1];
    int beg = g_rowstart[n];
    int end = g_rowstart[n + 1];
    float base = g_sdst[n] + c0;
    const unsigned FULL = 0xffffffffu;

    float a0 = 0.f, a1 = 0.f, den = 0.f;

    for (int i0 = beg; i0 < end; i0 += 32) {
        int rem = end - i0;
        if (rem > 32) rem = 32;
        int idx = i0 + (lane < rem ? lane : 0);
        int2 e = g_edge[idx];
        float v = g_ssrc[e.x] + base + c1 * __int_as_float(e.y);
        v = fmaxf(v, NEG_SLOPE * v);
        float x = (lane < rem) ? __expf(v) : 0.f;
        ebuf[wid][lane] = make_float2(x, __int_as_float(e.x));
        __syncwarp();

        int j = 0;
        for (; j + 8 <= rem; j += 8) {
            #pragma unroll
            for (int jj = 0; jj < 8; jj++) {
                float2 eb = ebuf[wid][j + jj];
                float xj = eb.x;
                int   sj = __float_as_int(eb.y);
                float2 zf = __half22float2(
                    *(const __half2*)(g_zh + (size_t)sj * 64 + 2 * lane));
                den += xj;
                a0 += xj * zf.x;
                a1 += xj * zf.y;
            }
        }
        for (; j < rem; j++) {
            float2 eb = ebuf[wid][j];
            float xj = eb.x;
            int   sj = __float_as_int(eb.y);
            float2 zf = __half22float2(
                *(const __half2*)(g_zh + (size_t)sj * 64 + 2 * lane));
            den += xj;
            a0 += xj * zf.x;
            a1 += xj * zf.y;
        }
        __syncwarp();
    }

    size_t o = (size_t)n * 64 + 2 * lane;
    float2 hv = *(const float2*)(g_h + o);
    float r0, r1;
    if (end > beg) {
        float inv = 1.0f / den;
        float2 hsv = *(const float2*)(g_hs + o);
        r0 = hsv.x + a0 * inv;
        r1 = hsv.y + a1 * inv;
    } else {
        r0 = hv.x; r1 = hv.y;
    }
    float hn0 = hv.x + fmaxf(r0, 0.f);
    float hn1 = hv.y + fmaxf(r1, 0.f);

    if (!layer) {
        *(float2*)(g_h + o) = make_float2(hn0, hn1);
    } else {
        float yv = 0.f;
        #pragma unroll
        for (int c = 0; c < 12; c++) {
            float2 wv = *(const float2*)&w_sm[c][2 * lane];
            float p = hn0 * wv.x + hn1 * wv.y;
            #pragma unroll
            for (int off = 16; off > 0; off >>= 1)
                p += __shfl_xor_sync(FULL, p, off);
            if (lane == c) yv = p + b_sm[c];
        }
        if (lane < 12) out[n * 12 + lane] = yv;
    }
}

// ---------------- launch -----------------------------------------------------
extern "C" void kernel_launch(void* const* d_in, const int* in_sizes, int n_in,
                              void* d_out, int out_size) {
    const float* feats   = (const float*)d_in[0];
    const float* e_w     = (const float*)d_in[1];
    const int*   src     = (const int*)d_in[4];
    const int*   dst     = (const int*)d_in[5];
    const float* emb_h_W = (const float*)d_in[6];
    const float* emb_h_b = (const float*)d_in[7];
    const float* emb_e_W = (const float*)d_in[8];
    const float* emb_e_b = (const float*)d_in[9];
    const float* W_self1 = (const float*)d_in[10];
    const float* W_func1 = (const float*)d_in[11];
    const float* attn1   = (const float*)d_in[12];
    const float* W_self2 = (const float*)d_in[13];
    const float* W_func2 = (const float*)d_in[14];
    const float* attn2   = (const float*)d_in[15];
    const float* lin1_W  = (const float*)d_in[16];
    const float* lin1_b  = (const float*)d_in[17];
    float* out = (float*)d_out;

    // ncu captures the 4th kernel launch -> k_agg(layer 0)
    k_pre<<<HB + EMB + 1, 256>>>(dst, feats, emb_h_W, emb_h_b,
                                 emb_e_W, emb_e_b, attn1, attn2);    // 0
    k_scan<<<NB_SCAN, 256>>>();                                      // 1
    k_sx<<<HB + XB2, 256>>>(src, dst, e_w, W_self1, W_func1, attn1); // 2
    k_agg<<<NN / 8, 256>>>(0, lin1_W, lin1_b, out);                  // 3 <- ncu
    k_xform2<<<XB2, 256>>>(W_self2, W_func2, attn2);                 // 4
    k_agg<<<NN / 8, 256>>>(1, lin1_W, lin1_b, out);                  // 5
}

// round 16
// speedup vs baseline: 1.1345x; 1.0307x over previous
#include <cuda_runtime.h>
#include <cuda_bf16.h>
#include <cuda_fp16.h>
#include <cstdint>

#define NN 100000
#define EE 1600000
#define DIN 24
#define DH 64
#define DOUT 12
#define NEG_SLOPE 0.01f

#define HB    (EE / 256)              // 6250 hist/scatter blocks
#define EMB   (NN / 32)               // 3125 embed blocks (32 nodes each)
#define NB_SCAN ((NN + 1023) / 1024)  // 98
#define XB2   ((NN + 127) / 128)      // 782 xform blocks (128 nodes each)

// ---------------- scratch (static device globals; allocation-free) -----------
__device__ __align__(16) float  g_h[NN * DH];    // current node features
__device__ __align__(16) float  g_hs[NN * DH];   // h @ W_self.T
__device__ __align__(16) __half g_zh[NN * DH];   // h @ W_func.T (fp16, for gathers)
__device__ float g_ssrc[NN];
__device__ float g_sdst[NN];
__device__ int   g_rowstart[NN + 1];
__device__ int   g_cursor[NN];                   // counts; returns to 0 after scatter
__device__ __align__(16) int2 g_edge[EE];        // (src, bitcast(e_w)) sorted by dst
__device__ int   g_flags[128];                   // scan-ready flags (reset by k_sx)
__device__ int   g_aggval[128];
__device__ float g_c[4];                         // {c1_l1, c0_l1, c1_l2, c0_l2}

#define LDSM4(r0, r1, r2, r3, addr) \
    asm volatile("ldmatrix.sync.aligned.m8n8.x4.shared.b16 {%0,%1,%2,%3},[%4];" \
                 : "=r"(r0), "=r"(r1), "=r"(r2), "=r"(r3) : "r"(addr))
#define LDSM2(r0, r1, addr) \
    asm volatile("ldmatrix.sync.aligned.m8n8.x2.shared.b16 {%0,%1},[%2];" \
                 : "=r"(r0), "=r"(r1) : "r"(addr))
#define MMA16816(c, a0, a1, a2, a3, b0, b1) \
    asm volatile("mma.sync.aligned.m16n8k16.row.col.f32.f16.f16.f32 " \
                 "{%0,%1,%2,%3},{%4,%5,%6,%7},{%8,%9},{%0,%1,%2,%3};" \
                 : "+f"((c)[0]), "+f"((c)[1]), "+f"((c)[2]), "+f"((c)[3]) \
                 : "r"(a0), "r"(a1), "r"(a2), "r"(a3), "r"(b0), "r"(b1))

// ---------------- fused: hist + input embedding + edge coeffs ----------------
__global__ __launch_bounds__(256) void k_pre(
    const int* __restrict__ dst, const float* __restrict__ feats,
    const float* __restrict__ W, const float* __restrict__ b,
    const float* __restrict__ eW, const float* __restrict__ eb,
    const float* __restrict__ a1, const float* __restrict__ a2) {
    __shared__ float w_sm[64 * 25];
    __shared__ float f_sm[32 * 25];
    __shared__ float b_sm[64];
    __shared__ float csh[4][64];
    int t = threadIdx.x;
    int blk = blockIdx.x;

    if (blk < HB) {
        int e = blk * 256 + t;
        atomicAdd(&g_cursor[dst[e]], 1);
    } else if (blk < HB + EMB) {
        int node0 = (blk - HB) * 32;
        for (int idx = t; idx < 64 * 24; idx += 256)
            w_sm[(idx / 24) * 25 + (idx % 24)] = W[idx];
        for (int idx = t; idx < 32 * 24; idx += 256)
            f_sm[(idx / 24) * 25 + (idx % 24)] = feats[(node0 + idx / 24) * 24 + (idx % 24)];
        if (t < 64) b_sm[t] = b[t];
        __syncthreads();
        int ch = t & 63, ng = t >> 6;   // 4 groups of 8 nodes
        float acc[8];
        #pragma unroll
        for (int nn = 0; nn < 8; nn++) acc[nn] = b_sm[ch];
        for (int k = 0; k < 24; k++) {
            float wv = w_sm[ch * 25 + k];
            #pragma unroll
            for (int nn = 0; nn < 8; nn++)
                acc[nn] += f_sm[(ng * 8 + nn) * 25 + k] * wv;
        }
        #pragma unroll
        for (int nn = 0; nn < 8; nn++)
            g_h[(size_t)(node0 + ng * 8 + nn) * 64 + ch] = acc[nn];
    } else {
        if (t < 64) {
            csh[0][t] = eW[t] * a1[128 + t];
            csh[1][t] = eb[t] * a1[128 + t];
            csh[2][t] = eW[t] * a2[128 + t];
            csh[3][t] = eb[t] * a2[128 + t];
        }
        __syncthreads();
        if (t < 4) {
            float s = 0.f;
            #pragma unroll
            for (int k = 0; k < 64; k++) s += csh[t][k];
            g_c[t] = s;
        }
    }
}

// ---------------- single-pass scan (parallel-poll lookback) ------------------
__global__ __launch_bounds__(256) void k_scan() {
    __shared__ int sh[256];
    __shared__ int sred[256];
    int t = threadIdx.x;
    int bid = blockIdx.x;
    int base = bid * 1024 + t * 4;
    int v[4];
    #pragma unroll
    for (int i = 0; i < 4; i++) v[i] = (base + i < NN) ? g_cursor[base + i] : 0;
    int s = v[0] + v[1] + v[2] + v[3];
    sh[t] = s;
    __syncthreads();
    for (int off = 1; off < 256; off <<= 1) {
        int x = 0;
        if (t >= off) x = sh[t - off];
        __syncthreads();
        if (t >= off) sh[t] += x;
        __syncthreads();
    }
    int total = sh[255];
    int run = sh[t] - s;

    if (t == 0) {
        g_aggval[bid] = total;
        __threadfence();
        atomicExch(&g_flags[bid], 1);
    }
    // parallel lookback: thread t polls predecessor t
    int myagg = 0;
    if (t < bid) {
        while (atomicAdd(&g_flags[t], 0) == 0) {}
        myagg = atomicAdd(&g_aggval[t], 0);
    }
    sred[t] = myagg;
    __syncthreads();
    #pragma unroll
    for (int sft = 128; sft > 0; sft >>= 1) {
        if (t < sft) sred[t] += sred[t + sft];
        __syncthreads();
    }
    int add = sred[0];
    #pragma unroll
    for (int i = 0; i < 4; i++) {
        if (base + i < NN) g_rowstart[base + i] = add + run;
        run += v[i];
    }
    if (bid == 0 && t == 0) g_rowstart[NN] = EE;
}

// ---------------- xform body (fp16 HMMA, 128 nodes) --------------------------
__device__ __forceinline__ void xform_body(int node0, const float* __restrict__ Wself,
                                           const float* __restrict__ Wfunc,
                                           const float* __restrict__ attn,
                                           __half* hSm, __half* wSm) {
    int t = threadIdx.x;

    {
        int node = t >> 1;
        int k0 = (t & 1) * 32;
        int gn = node0 + node;
        #pragma unroll
        for (int i = 0; i < 8; i++) {
            float4 f = (gn < NN) ? *(const float4*)(g_h + (size_t)gn * 64 + k0 + i * 4)
                                 : make_float4(0.f, 0.f, 0.f, 0.f);
            *(__half2*)(hSm + node * 72 + k0 + i * 4)     = __floats2half2_rn(f.x, f.y);
            *(__half2*)(hSm + node * 72 + k0 + i * 4 + 2) = __floats2half2_rn(f.z, f.w);
        }
    }
    {
        int row = t >> 1;
        int k0 = (t & 1) * 32;
        const float* Wr = (row < 64) ? (Wself + row * 64) : (Wfunc + (row - 64) * 64);
        #pragma unroll
        for (int i = 0; i < 8; i++) {
            float4 f = *(const float4*)(Wr + k0 + i * 4);
            *(__half2*)(wSm + row * 72 + k0 + i * 4)     = __floats2half2_rn(f.x, f.y);
            *(__half2*)(wSm + row * 72 + k0 + i * 4 + 2) = __floats2half2_rn(f.z, f.w);
        }
    }
    __syncthreads();

    int w = t >> 5, lane = t & 31;
    int mtp = w & 3;
    int mh = w >> 2;

    uint32_t aB0 = (uint32_t)__cvta_generic_to_shared(
        hSm + (mtp * 16 + (lane & 15)) * 72 + ((lane >> 4) << 3));
    uint32_t aB1 = aB0 + (uint32_t)(64 * 72 * 2);
    uint32_t bB = (uint32_t)__cvta_generic_to_shared(
        wSm + (mh * 64 + (lane & 7)) * 72 + (((lane >> 3) & 1) << 3));

    float acc[2][8][4];
    #pragma unroll
    for (int m = 0; m < 2; m++)
        #pragma unroll
        for (int nt = 0; nt < 8; nt++)
            #pragma unroll
            for (int i = 0; i < 4; i++) acc[m][nt][i] = 0.f;

    #pragma unroll
    for (int ks = 0; ks < 4; ks++) {
        uint32_t a00, a01, a02, a03, a10, a11, a12, a13;
        LDSM4(a00, a01, a02, a03, aB0 + ks * 32);
        LDSM4(a10, a11, a12, a13, aB1 + ks * 32);
        #pragma unroll
        for (int nt = 0; nt < 8; nt++) {
            uint32_t b0, b1;
            LDSM2(b0, b1, bB + nt * (8 * 72 * 2) + ks * 32);
            MMA16816(acc[0][nt], a00, a01, a02, a03, b0, b1);
            MMA16816(acc[1][nt], a10, a11, a12, a13, b0, b1);
        }
    }

    int row = lane >> 2;
    int col2 = (lane & 3) * 2;
    const unsigned FULL = 0xffffffffu;

    #pragma unroll
    for (int m = 0; m < 2; m++) {
        int gnl = node0 + (mtp + m * 4) * 16 + row;
        int gnh = gnl + 8;
        if (mh == 0) {
            #pragma unroll
            for (int nt = 0; nt < 8; nt++) {
                int ch = nt * 8 + col2;
                if (gnl < NN)
                    *(float2*)(g_hs + (size_t)gnl * 64 + ch) =
                        make_float2(acc[m][nt][0], acc[m][nt][1]);
                if (gnh < NN)
                    *(float2*)(g_hs + (size_t)gnh * 64 + ch) =
                        make_float2(acc[m][nt][2], acc[m][nt][3]);
            }
        } else {
            float psl = 0.f, psh = 0.f, pdl = 0.f, pdh = 0.f;
            #pragma unroll
            for (int nt = 0; nt < 8; nt++) {
                int chF = nt * 8 + col2;
                if (gnl < NN)
                    *(__half2*)(g_zh + (size_t)gnl * 64 + chF) =
                        __floats2half2_rn(acc[m][nt][0], acc[m][nt][1]);
                if (gnh < NN)
                    *(__half2*)(g_zh + (size_t)gnh * 64 + chF) =
                        __floats2half2_rn(acc[m][nt][2], acc[m][nt][3]);
                float as0 = attn[chF], as1 = attn[chF + 1];
                float ad0 = attn[64 + chF], ad1 = attn[64 + chF + 1];
                psl += acc[m][nt][0] * as0 + acc[m][nt][1] * as1;
                psh += acc[m][nt][2] * as0 + acc[m][nt][3] * as1;
                pdl += acc[m][nt][0] * ad0 + acc[m][nt][1] * ad1;
                pdh += acc[m][nt][2] * ad0 + acc[m][nt][3] * ad1;
            }
            #pragma unroll
            for (int off = 1; off <= 2; off <<= 1) {
                psl += __shfl_xor_sync(FULL, psl, off);
                psh += __shfl_xor_sync(FULL, psh, off);
                pdl += __shfl_xor_sync(FULL, pdl, off);
                pdh += __shfl_xor_sync(FULL, pdh, off);
            }
            if ((lane & 3) == 0) {
                if (gnl < NN) { g_ssrc[gnl] = psl; g_sdst[gnl] = pdl; }
                if (gnh < NN) { g_ssrc[gnh] = psh; g_sdst[gnh] = pdh; }
            }
        }
    }
}

// ---------------- fused: scatter + xform layer 1 + flag reset ----------------
__global__ __launch_bounds__(256) void k_sx(const int* __restrict__ src,
                                            const int* __restrict__ dst,
                                            const float* __restrict__ ew,
                                            const float* __restrict__ Wself,
                                            const float* __restrict__ Wfunc,
                                            const float* __restrict__ attn) {
    __shared__ __half hSm[128 * 72];
    __shared__ __half wSm[128 * 72];
    int blk = blockIdx.x;
    if (blk < HB) {
        if (blk == 0 && threadIdx.x < 128) g_flags[threadIdx.x] = 0;
        int e = blk * 256 + threadIdx.x;
        int d = dst[e];
        int p = g_rowstart[d] + atomicSub(&g_cursor[d], 1) - 1;  // cursor -> 0
        g_edge[p] = make_int2(src[e], __float_as_int(ew[e]));
    } else {
        xform_body((blk - HB) * 128, Wself, Wfunc, attn, hSm, wSm);
    }
}

// ---------------- xform layer 2 ----------------------------------------------
__global__ __launch_bounds__(256) void k_xform2(const float* __restrict__ Wself,
                                                const float* __restrict__ Wfunc,
                                                const float* __restrict__ attn) {
    __shared__ __half hSm[128 * 72];
    __shared__ __half wSm[128 * 72];
    xform_body(blockIdx.x * 128, Wself, Wfunc, attn, hSm, wSm);
}

// ---------------- edge aggregation (2 warps per node) ------------------------
// Node's edge list split in half across a warp pair; each warp runs the
// R14 batch loop (smem edge broadcast, 8-deep z-gathers); halves combine
// via smem, warp 0 of the pair does the node epilogue.
__global__ __launch_bounds__(256) void k_agg(int layer, const float* __restrict__ linW,
                                             const float* __restrict__ linb,
                                             float* __restrict__ out) {
    __shared__ float w_sm[12][64];
    __shared__ float b_sm[12];
    __shared__ __align__(8) float2 ebuf[8][32];   // per-warp (x, bitcast src)
    __shared__ float part[8][66];                 // a0[0:32], a1[32:64], den[64]
    int t = threadIdx.x;
    if (layer) {
        for (int idx = t; idx < 12 * 64; idx += 256)
            w_sm[idx >> 6][idx & 63] = linW[idx];
        if (t < 12) b_sm[t] = linb[t];
    }
    __syncthreads();

    int w = t >> 5;
    int lane = t & 31;
    int pairi = t >> 6;        // node within block (0..3)
    int widx = (t >> 5) & 1;   // which half of the edge list
    int n = blockIdx.x * 4 + pairi;
    float c1 = g_c[layer * 2 + 0];
    float c0 = g_c[layer * 2 + 1];
    int beg = g_rowstart[n];
    int end = g_rowstart[n + 1];
    int deg = end - beg;
    int halfc = (deg + 1) >> 1;
    int mybeg = beg + widx * halfc;
    int myend = widx ? end : (beg + halfc);
    float base = g_sdst[n] + c0;
    const unsigned FULL = 0xffffffffu;

    float a0 = 0.f, a1 = 0.f, den = 0.f;

    for (int i0 = mybeg; i0 < myend; i0 += 32) {
        int rem = myend - i0;
        if (rem > 32) rem = 32;
        int idx = i0 + (lane < rem ? lane : 0);
        int2 e = g_edge[idx];
        float v = g_ssrc[e.x] + base + c1 * __int_as_float(e.y);
        v = fmaxf(v, NEG_SLOPE * v);
        float x = (lane < rem) ? __expf(v) : 0.f;
        ebuf[w][lane] = make_float2(x, __int_as_float(e.x));
        __syncwarp();

        int j = 0;
        for (; j + 8 <= rem; j += 8) {
            #pragma unroll
            for (int jj = 0; jj < 8; jj++) {
                float2 eb = ebuf[w][j + jj];
                float xj = eb.x;
                int   sj = __float_as_int(eb.y);
                float2 zf = __half22float2(
                    *(const __half2*)(g_zh + (size_t)sj * 64 + 2 * lane));
                den += xj;
                a0 += xj * zf.x;
                a1 += xj * zf.y;
            }
        }
        for (; j < rem; j++) {
            float2 eb = ebuf[w][j];
            float xj = eb.x;
            int   sj = __float_as_int(eb.y);
            float2 zf = __half22float2(
                *(const __half2*)(g_zh + (size_t)sj * 64 + 2 * lane));
            den += xj;
            a0 += xj * zf.x;
            a1 += xj * zf.y;
        }
        __syncwarp();
    }

    // combine warp pair
    part[w][lane] = a0;
    part[w][32 + lane] = a1;
    if (lane == 0) part[w][64] = den;
    __syncthreads();

    if (widx == 0) {
        a0 += part[w + 1][lane];
        a1 += part[w + 1][32 + lane];
        den += part[w + 1][64];

        size_t o = (size_t)n * 64 + 2 * lane;
        float2 hv = *(const float2*)(g_h + o);
        float r0, r1;
        if (deg > 0) {
            float inv = 1.0f / den;
            float2 hsv = *(const float2*)(g_hs + o);
            r0 = hsv.x + a0 * inv;
            r1 = hsv.y + a1 * inv;
        } else {
            r0 = hv.x; r1 = hv.y;
        }
        float hn0 = hv.x + fmaxf(r0, 0.f);
        float hn1 = hv.y + fmaxf(r1, 0.f);

        if (!layer) {
            *(float2*)(g_h + o) = make_float2(hn0, hn1);
        } else {
            float yv = 0.f;
            #pragma unroll
            for (int c = 0; c < 12; c++) {
                float2 wv = *(const float2*)&w_sm[c][2 * lane];
                float p = hn0 * wv.x + hn1 * wv.y;
                #pragma unroll
                for (int off = 16; off > 0; off >>= 1)
                    p += __shfl_xor_sync(FULL, p, off);
                if (lane == c) yv = p + b_sm[c];
            }
            if (lane < 12) out[n * 12 + lane] = yv;
        }
    }
}

// ---------------- launch -----------------------------------------------------
extern "C" void kernel_launch(void* const* d_in, const int* in_sizes, int n_in,
                              void* d_out, int out_size) {
    const float* feats   = (const float*)d_in[0];
    const float* e_w     = (const float*)d_in[1];
    const int*   src     = (const int*)d_in[4];
    const int*   dst     = (const int*)d_in[5];
    const float* emb_h_W = (const float*)d_in[6];
    const float* emb_h_b = (const float*)d_in[7];
    const float* emb_e_W = (const float*)d_in[8];
    const float* emb_e_b = (const float*)d_in[9];
    const float* W_self1 = (const float*)d_in[10];
    const float* W_func1 = (const float*)d_in[11];
    const float* attn1   = (const float*)d_in[12];
    const float* W_self2 = (const float*)d_in[13];
    const float* W_func2 = (const float*)d_in[14];
    const float* attn2   = (const float*)d_in[15];
    const float* lin1_W  = (const float*)d_in[16];
    const float* lin1_b  = (const float*)d_in[17];
    float* out = (float*)d_out;

    // ncu captures the 4th kernel launch -> k_agg(layer 0)
    k_pre<<<HB + EMB + 1, 256>>>(dst, feats, emb_h_W, emb_h_b,
                                 emb_e_W, emb_e_b, attn1, attn2);    // 0
    k_scan<<<NB_SCAN, 256>>>();                                      // 1
    k_sx<<<HB + XB2, 256>>>(src, dst, e_w, W_self1, W_func1, attn1); // 2
    k_agg<<<NN / 4, 256>>>(0, lin1_W, lin1_b, out);                  // 3 <- ncu
    k_xform2<<<XB2, 256>>>(W_self2, W_func2, attn2);                 // 4
    k_agg<<<NN / 4, 256>>>(1, lin1_W, lin1_b, out);                  // 5
}